// round 16
// baseline (speedup 1.0000x reference)
#include <cuda_runtime.h>
#include <cuda_fp16.h>
#include <cstdint>

// Problem constants
#define NE 16
#define NT 512
#define NH 2048
#define NI 1408
#define NK 6
#define NPAIR (NT * NK)   // 3072
#define QB 128

// fp16 tile row stride 80 bytes (bank-conflict-free for ldmatrix:
// row base banks = 20*r mod 32 -> 8 consecutive rows all distinct)
#define HSTRIDE 80
#define HTILE   (128 * HSTRIDE)   // 10240
#define HSTG    (2 * HTILE)       // gemm2 stage: A + W
#define HSTG1   (3 * HTILE)       // gemm1 stage: A + G + U

// ---------------- scratch (device globals) ----------------------------------
__device__ int   g_cnt[NE];
__device__ int   g_off[NE];
__device__ int   g_list[NPAIR];
__device__ uint4 g_xh_raw[(size_t)NT * NH / 8];         // x in fp16
__device__ uint4 g_hact_raw[(size_t)NPAIR * NI / 8];    // SwiGLU act fp16 (sorted)
__device__ uint4 g_ypair_raw[(size_t)NPAIR * NH / 8];   // per-pair output fp16

#define g_xh    ((__half*)g_xh_raw)
#define g_hact  ((__half*)g_hact_raw)
#define g_ypair ((__half*)g_ypair_raw)

// ---------------- helpers ----------------------------------------------------
__device__ __forceinline__ uint32_t smem_u32(const void* p) {
    uint32_t a;
    asm("{ .reg .u64 t; cvta.to.shared.u64 t, %1; cvt.u32.u64 %0, t; }"
        : "=r"(a) : "l"(p));
    return a;
}

__device__ __forceinline__ void ldm4(uint32_t addr, uint32_t* r) {
    asm volatile("ldmatrix.sync.aligned.m8n8.x4.shared.b16 {%0,%1,%2,%3}, [%4];"
                 : "=r"(r[0]), "=r"(r[1]), "=r"(r[2]), "=r"(r[3]) : "r"(addr));
}

__device__ __forceinline__ void mma16(float* c, const uint32_t* a,
                                      uint32_t b0, uint32_t b1) {
    asm volatile(
        "mma.sync.aligned.m16n8k16.row.col.f32.f16.f16.f32 "
        "{%0,%1,%2,%3}, {%4,%5,%6,%7}, {%8,%9}, {%0,%1,%2,%3};"
        : "+f"(c[0]), "+f"(c[1]), "+f"(c[2]), "+f"(c[3])
        : "r"(a[0]), "r"(a[1]), "r"(a[2]), "r"(a[3]), "r"(b0), "r"(b1));
}

__device__ __forceinline__ uint2 pack_h4(const float4& v) {
    __half2 h0 = __floats2half2_rn(v.x, v.y);
    __half2 h1 = __floats2half2_rn(v.z, v.w);
    uint2 r;
    r.x = *(const uint32_t*)&h0;
    r.y = *(const uint32_t*)&h1;
    return r;
}

__device__ __forceinline__ void sts_u2(uint32_t addr, uint2 v) {
    asm volatile("st.shared.v2.b32 [%0], {%1,%2};"
                 :: "r"(addr), "r"(v.x), "r"(v.y) : "memory");
}

#define CPA16(dst, src, sz) \
    asm volatile("cp.async.cg.shared.global [%0], [%1], 16, %2;" \
                 :: "r"(dst), "l"(src), "r"(sz) : "memory")
#define CPC()  asm volatile("cp.async.commit_group;" ::: "memory")
#define CPW0() asm volatile("cp.async.wait_group 0;" ::: "memory")

// ---------------- routing ----------------------------------------------------
__global__ void routing_kernel(const int* __restrict__ sel) {
    __shared__ int s_cnt[NE], s_off[NE], s_cur[NE];
    const int tid = threadIdx.x;
    if (tid < NE) s_cnt[tid] = 0;
    __syncthreads();
    for (int p = tid; p < NPAIR; p += blockDim.x)
        atomicAdd(&s_cnt[sel[p]], 1);
    __syncthreads();
    if (tid == 0) {
        int acc = 0;
        for (int e = 0; e < NE; e++) { s_off[e] = acc; acc += s_cnt[e]; s_cur[e] = 0; }
    }
    __syncthreads();
    for (int p = tid; p < NPAIR; p += blockDim.x) {
        int e = sel[p];
        int pos = atomicAdd(&s_cur[e], 1);
        g_list[s_off[e] + pos] = p;
    }
    if (tid < NE) { g_cnt[tid] = s_cnt[tid]; g_off[tid] = s_off[tid]; }
}

// ---------------- x -> fp16 pre-pass -----------------------------------------
__global__ void xcvt_kernel(const float* __restrict__ x) {
    const int i = blockIdx.x * blockDim.x + threadIdx.x;
    if (i >= NT * NH / 8) return;
    const float4 v0 = *(const float4*)(x + (size_t)i * 8);
    const float4 v1 = *(const float4*)(x + (size_t)i * 8 + 4);
    uint2 a = pack_h4(v0), b = pack_h4(v1);
    uint4 o; o.x = a.x; o.y = a.y; o.z = b.x; o.w = b.y;
    g_xh_raw[i] = o;
}

extern __shared__ char dynsm[];

// ---------------- GEMM1: gate+up fused, 128x128 CTA, 2m x 4n (R13 proven) ----
__global__ void __launch_bounds__(256) gemm1_kernel(
    int ebase,
    const float* __restrict__ wg, const float* __restrict__ sg,
    const float* __restrict__ wu, const float* __restrict__ su)
{
    const int e   = ebase + blockIdx.z;
    const int cnt = g_cnt[e];
    const int m0  = blockIdx.y * 128;
    if (m0 >= cnt) return;
    const int eoff = g_off[e];
    const int n0   = blockIdx.x * 128;
    const int tid  = threadIdx.x;

    int* s_tok = (int*)dynsm;
    const uint32_t hb = smem_u32(dynsm) + 1024;

    if (tid < 128) {
        int mi = m0 + tid;
        s_tok[tid] = (mi < cnt) ? (g_list[eoff + mi] / NK) : -1;
    }
    __syncthreads();

    const float* wge = wg + (size_t)e * NI * NH + (size_t)n0 * NH;
    const float* wue = wu + (size_t)e * NI * NH + (size_t)n0 * NH;
    const int scb = e * (NI / QB) * (NH / QB) + (n0 >> 7) * (NH / QB);

    // weight staging packed to fp16 at LDG (gemm2's proven pattern)
    uint2 Rg[4], Ru[4];
    const int ldrow = tid >> 3, ldcc = tid & 7;

    auto ldgW = [&](int c) {
        const int k0 = c * 32;
#pragma unroll
        for (int it = 0; it < 4; ++it) {
            const int row = ldrow + it * 32;
            Rg[it] = pack_h4(*(const float4*)(wge + (size_t)row * NH + k0 + (ldcc << 2)));
            Ru[it] = pack_h4(*(const float4*)(wue + (size_t)row * NH + k0 + (ldcc << 2)));
        }
    };
    auto stsW = [&](uint32_t stage) {
#pragma unroll
        for (int it = 0; it < 4; ++it) {
            const uint32_t off = (uint32_t)((ldrow + it * 32) * HSTRIDE + ldcc * 8);
            sts_u2(stage + HTILE + off, Rg[it]);
            sts_u2(stage + 2 * HTILE + off, Ru[it]);
        }
    };
    auto cpaA = [&](int c, uint32_t stage) {
        const int k0 = c * 32;
#pragma unroll
        for (int it = 0; it < 2; ++it) {
            const int idx = tid + (it << 8);
            const int row = idx >> 2, cc = idx & 3;
            const int tok = s_tok[row];
            const __half* src = g_xh + (size_t)(tok >= 0 ? tok : 0) * NH + k0 + cc * 8;
            CPA16(stage + (uint32_t)(row * HSTRIDE + cc * 16), src, (tok >= 0) ? 16 : 0);
        }
        CPC();
    };

    const int lane = tid & 31, warp = tid >> 5;
    const int gq = lane >> 2, tq = lane & 3;
    const int wm = warp & 1, wn = warp >> 1;   // 2 m-warps x 4 n-warps (64x32 tiles)
    const int lrow = lane & 15, lcol = (lane >> 4) << 4;

    float accG[4][4][4];
    float accU[4][4][4];
#pragma unroll
    for (int mi = 0; mi < 4; mi++)
#pragma unroll
        for (int ni = 0; ni < 4; ni++)
#pragma unroll
            for (int q = 0; q < 4; q++) { accG[mi][ni][q] = 0.f; accU[mi][ni][q] = 0.f; }

    float sg_c = __ldg(sg + scb);
    float su_c = __ldg(su + scb);

    const int C = NH / 32;   // 64 chunks, 4 per quant block

    ldgW(0);
    stsW(hb);
    cpaA(0, hb);
    ldgW(1);
    CPW0();
    __syncthreads();

    for (int c = 0; c < C; ++c) {
        const uint32_t Ss = hb + (uint32_t)((c & 1) * HSTG1);
        const uint32_t So = hb + (uint32_t)(((c + 1) & 1) * HSTG1);
        if (c + 1 < C) {
            stsW(So);                 // regs hold chunk c+1
            cpaA(c + 1, So);
            if (c + 2 < C) ldgW(c + 2);
        }

        const uint32_t hA = Ss, hG = Ss + HTILE, hU = Ss + 2 * HTILE;
#pragma unroll
        for (int ks = 0; ks < 2; ks++) {
            const uint32_t kc = (uint32_t)(ks * 32 + lcol);
            uint32_t a[4][4];
#pragma unroll
            for (int mi = 0; mi < 4; mi++)
                ldm4(hA + (uint32_t)((wm * 64 + mi * 16 + lrow) * HSTRIDE) + kc, a[mi]);
#pragma unroll
            for (int nbg = 0; nbg < 2; nbg++) {
                const uint32_t rowb = (uint32_t)((wn * 32 + nbg * 16 + lrow) * HSTRIDE) + kc;
                uint32_t g[4], u[4];
                ldm4(hG + rowb, g);
                ldm4(hU + rowb, u);
#pragma unroll
                for (int mi = 0; mi < 4; mi++) {
                    mma16(accG[mi][2 * nbg + 0], a[mi], g[0], g[2]);
                    mma16(accG[mi][2 * nbg + 1], a[mi], g[1], g[3]);
                    mma16(accU[mi][2 * nbg + 0], a[mi], u[0], u[2]);
                    mma16(accU[mi][2 * nbg + 1], a[mi], u[1], u[3]);
                }
            }
        }

        if ((c & 3) == 3 && c + 1 < C) {
            const int b = (c >> 2) + 1;
            const float sgn = __ldg(sg + scb + b);
            const float sun = __ldg(su + scb + b);
            const float rg = sg_c / sgn, ru = su_c / sun;
            sg_c = sgn; su_c = sun;
#pragma unroll
            for (int mi = 0; mi < 4; mi++)
#pragma unroll
                for (int ni = 0; ni < 4; ni++)
#pragma unroll
                    for (int q = 0; q < 4; q++) {
                        accG[mi][ni][q] *= rg;
                        accU[mi][ni][q] *= ru;
                    }
        }

        if (c + 1 < C) CPW0();
        __syncthreads();
    }

    // epilogue: final scale + SwiGLU -> fp16 sorted activations
#pragma unroll
    for (int mi = 0; mi < 4; mi++) {
#pragma unroll
        for (int half = 0; half < 2; half++) {
            const int rr = wm * 64 + mi * 16 + gq + half * 8;
            const int gm = m0 + rr;
            if (gm < cnt) {
                __half* dst = g_hact + (size_t)(eoff + gm) * NI + n0 + wn * 32 + 2 * tq;
#pragma unroll
                for (int ni = 0; ni < 4; ni++) {
                    float g0 = accG[mi][ni][half * 2 + 0] * sg_c;
                    float g1 = accG[mi][ni][half * 2 + 1] * sg_c;
                    float u0 = accU[mi][ni][half * 2 + 0] * su_c;
                    float u1 = accU[mi][ni][half * 2 + 1] * su_c;
                    float h0 = g0 / (1.f + __expf(-g0)) * u0;
                    float h1 = g1 / (1.f + __expf(-g1)) * u1;
                    __half2 h = __floats2half2_rn(h0, h1);
                    *(uint32_t*)(dst + ni * 8) = *(uint32_t*)&h;
                }
            }
        }
    }
}

// ---------------- GEMM2: down proj (R7 proven), fp16 ypair output ------------
__global__ void __launch_bounds__(256, 2) gemm2_kernel(
    int ebase,
    const float* __restrict__ wd, const float* __restrict__ sd,
    const float* __restrict__ rw)
{
    const int e   = ebase + blockIdx.z;
    const int cnt = g_cnt[e];
    const int m0  = blockIdx.y * 128;
    if (m0 >= cnt) return;
    const int eoff = g_off[e];
    const int n0   = blockIdx.x * 128;
    const int tid  = threadIdx.x;

    int*   s_pair = (int*)dynsm;
    float* s_rw   = (float*)(dynsm + 512);
    const uint32_t hb = smem_u32(dynsm) + 1024;

    if (tid < 128) {
        int mi = m0 + tid;
        int p = (mi < cnt) ? g_list[eoff + mi] : -1;
        s_pair[tid] = p;
        s_rw[tid]   = (p >= 0) ? rw[p] : 0.f;
    }
    __syncthreads();

    const float* wde = wd + (size_t)e * NH * NI + (size_t)n0 * NI;
    const int scb = e * (NH / QB) * (NI / QB) + (n0 >> 7) * (NI / QB);

    uint2 Rb[4];
    const int ldrow = tid >> 3, ldcc = tid & 7;

    auto ldgW = [&](int c) {
        const int k0 = c * 32;
#pragma unroll
        for (int it = 0; it < 4; ++it)
            Rb[it] = pack_h4(*(const float4*)(wde + (size_t)(ldrow + it * 32) * NI + k0 + (ldcc << 2)));
    };
    auto stsW = [&](uint32_t stage) {
#pragma unroll
        for (int it = 0; it < 4; ++it)
            sts_u2(stage + HTILE + (uint32_t)((ldrow + it * 32) * HSTRIDE + ldcc * 8), Rb[it]);
    };
    auto cpaA = [&](int c, uint32_t stage) {
        const int k0 = c * 32;
#pragma unroll
        for (int it = 0; it < 2; ++it) {
            const int idx = tid + (it << 8);
            const int row = idx >> 2, cc = idx & 3;
            const int ok = (m0 + row < cnt) ? 16 : 0;
            const __half* src = g_hact + (size_t)(eoff + m0 + row) * NI + k0 + cc * 8;
            CPA16(stage + (uint32_t)(row * HSTRIDE + cc * 16), src, ok);
        }
        CPC();
    };

    const int lane = tid & 31, warp = tid >> 5;
    const int gq = lane >> 2, tq = lane & 3;
    const int wm = warp & 3, wn = warp >> 2;   // 4 m-warps x 2 n-warps
    const int lrow = lane & 15, lcol = (lane >> 4) << 4;

    float acc[2][8][4];
#pragma unroll
    for (int mi = 0; mi < 2; mi++)
#pragma unroll
        for (int ni = 0; ni < 8; ni++)
#pragma unroll
            for (int q = 0; q < 4; q++) acc[mi][ni][q] = 0.f;

    float sd_c = __ldg(sd + scb);

    const int C = NI / 32;   // 44 chunks

    ldgW(0);
    stsW(hb);
    cpaA(0, hb);
    ldgW(1);
    CPW0();
    __syncthreads();

    for (int c = 0; c < C; ++c) {
        const uint32_t Ss = hb + (uint32_t)((c & 1) * HSTG);
        const uint32_t So = hb + (uint32_t)(((c + 1) & 1) * HSTG);
        if (c + 1 < C) {
            stsW(So);
            cpaA(c + 1, So);
            if (c + 2 < C) ldgW(c + 2);
        }

        const uint32_t hA = Ss, hB = Ss + HTILE;
#pragma unroll
        for (int ks = 0; ks < 2; ks++) {
            const uint32_t kc = (uint32_t)(ks * 32 + lcol);
            uint32_t a[2][4];
#pragma unroll
            for (int mi = 0; mi < 2; mi++)
                ldm4(hA + (uint32_t)((wm * 32 + mi * 16 + lrow) * HSTRIDE) + kc, a[mi]);
#pragma unroll
            for (int nb = 0; nb < 4; nb++) {
                const uint32_t rowb = (uint32_t)((wn * 64 + nb * 16 + lrow) * HSTRIDE) + kc;
                uint32_t b[4];
                ldm4(hB + rowb, b);
#pragma unroll
                for (int mi = 0; mi < 2; mi++) {
                    mma16(acc[mi][2 * nb + 0], a[mi], b[0], b[2]);
                    mma16(acc[mi][2 * nb + 1], a[mi], b[1], b[3]);
                }
            }
        }

        if ((c & 3) == 3 && c + 1 < C) {
            const int b = (c >> 2) + 1;
            const float sdn = __ldg(sd + scb + b);
            const float rsc = sd_c / sdn;
            sd_c = sdn;
#pragma unroll
            for (int mi = 0; mi < 2; mi++)
#pragma unroll
                for (int ni = 0; ni < 8; ni++)
#pragma unroll
                    for (int q = 0; q < 4; q++) acc[mi][ni][q] *= rsc;
        }

        if (c + 1 < C) CPW0();
        __syncthreads();
    }

#pragma unroll
    for (int mi = 0; mi < 2; mi++) {
#pragma unroll
        for (int half = 0; half < 2; half++) {
            const int rr = wm * 32 + mi * 16 + gq + half * 8;
            const int gm = m0 + rr;
            if (gm < cnt) {
                const int p = s_pair[gm - m0];
                const float w = s_rw[gm - m0] * sd_c;
                if (p >= 0) {
                    __half* dst = g_ypair + (size_t)p * NH + n0 + wn * 64 + 2 * tq;
#pragma unroll
                    for (int ni = 0; ni < 8; ni++) {
                        __half2 h = __floats2half2_rn(acc[mi][ni][half * 2 + 0] * w,
                                                      acc[mi][ni][half * 2 + 1] * w);
                        *(uint32_t*)(dst + ni * 8) = *(uint32_t*)&h;
                    }
                }
            }
        }
    }
}

// ---------------- combine (fp16 ypair -> fp32 out) ---------------------------
__global__ void combine_kernel(float* __restrict__ out) {
    const int idx = blockIdx.x * blockDim.x + threadIdx.x;
    if (idx >= NT * NH / 4) return;
    const int t  = idx / (NH / 4);
    const int h4 = idx - t * (NH / 4);
    float4 s = make_float4(0.f, 0.f, 0.f, 0.f);
#pragma unroll
    for (int k = 0; k < NK; k++) {
        const uint2 v = *(const uint2*)(g_ypair + (size_t)(t * NK + k) * NH + h4 * 4);
        const __half2 a = *(const __half2*)&v.x;
        const __half2 b = *(const __half2*)&v.y;
        s.x += __low2float(a); s.y += __high2float(a);
        s.z += __low2float(b); s.w += __high2float(b);
    }
    *(float4*)(out + (size_t)t * NH + h4 * 4) = s;
}

// ---------------- launch -----------------------------------------------------
#define SMEM1 (1024 + 2 * HSTG1)  // 62464
#define SMEM2 (1024 + 2 * HSTG)   // 41984

extern "C" void kernel_launch(void* const* d_in, const int* in_sizes, int n_in,
                              void* d_out, int out_size) {
    const float* x   = (const float*)d_in[0];
    const float* gw  = (const float*)d_in[1];
    const float* gsc = (const float*)d_in[2];
    const float* uw  = (const float*)d_in[3];
    const float* usc = (const float*)d_in[4];
    const float* dw  = (const float*)d_in[5];
    const float* dsc = (const float*)d_in[6];
    const float* rw  = (const float*)d_in[7];
    const int*   sel = (const int*)d_in[8];
    float* out = (float*)d_out;

    static cudaStream_t s2 = nullptr;
    static cudaEvent_t  evF = nullptr, evJ = nullptr;
    static int configured = 0;
    if (!configured) {
        cudaFuncSetAttribute(gemm1_kernel, cudaFuncAttributeMaxDynamicSharedMemorySize, SMEM1);
        cudaFuncSetAttribute(gemm2_kernel, cudaFuncAttributeMaxDynamicSharedMemorySize, SMEM2);
        cudaStreamCreateWithFlags(&s2, cudaStreamNonBlocking);
        cudaEventCreateWithFlags(&evF, cudaEventDisableTiming);
        cudaEventCreateWithFlags(&evJ, cudaEventDisableTiming);
        configured = 1;
    }

    routing_kernel<<<1, 256>>>(sel);
    xcvt_kernel<<<(NT * NH / 8 + 255) / 256, 256>>>(x);

    // fork: side stream handles experts 8..15
    cudaEventRecord(evF, 0);
    cudaStreamWaitEvent(s2, evF, 0);

    dim3 g1(NI / 128, NPAIR / 128, NE / 2);   // (11, 24, 8)
    gemm1_kernel<<<g1, 256, SMEM1, 0 >>>(0, gw, gsc, uw, usc);
    gemm1_kernel<<<g1, 256, SMEM1, s2>>>(8, gw, gsc, uw, usc);

    dim3 g2(NH / 128, NPAIR / 128, NE / 2);   // (16, 24, 8)
    gemm2_kernel<<<g2, 256, SMEM2, 0 >>>(0, dw, dsc, rw);
    gemm2_kernel<<<g2, 256, SMEM2, s2>>>(8, dw, dsc, rw);

    // join
    cudaEventRecord(evJ, s2);
    cudaStreamWaitEvent(0, evJ, 0);

    combine_kernel<<<(NT * NH / 4 + 255) / 256, 256>>>(out);
}

// round 17
// speedup vs baseline: 1.4002x; 1.4002x over previous
#include <cuda_runtime.h>
#include <cuda_fp16.h>
#include <cstdint>

// Problem constants
#define NE 16
#define NT 512
#define NH 2048
#define NI 1408
#define NK 6
#define NPAIR (NT * NK)   // 3072
#define QB 128

// fp16 tile row stride 80 bytes (bank-conflict-free for ldmatrix:
// row base banks = 20*r mod 32 -> 8 consecutive rows all distinct)
#define HSTRIDE 80
#define HTILE   (128 * HSTRIDE)   // 10240
#define HSTG    (2 * HTILE)       // gemm2 stage: A + W
#define HSTG1   (3 * HTILE)       // gemm1 stage: A + G + U

// ---------------- scratch (device globals) ----------------------------------
__device__ int   g_cnt[NE];
__device__ int   g_off[NE];
__device__ int   g_list[NPAIR];
__device__ uint4 g_xh_raw[(size_t)NT * NH / 8];         // x in fp16
__device__ uint4 g_hact_raw[(size_t)NPAIR * NI / 8];    // SwiGLU act fp16 (sorted)
__device__ uint4 g_ypair_raw[(size_t)NPAIR * NH / 8];   // per-pair output fp16

#define g_xh    ((__half*)g_xh_raw)
#define g_hact  ((__half*)g_hact_raw)
#define g_ypair ((__half*)g_ypair_raw)

// ---------------- helpers ----------------------------------------------------
__device__ __forceinline__ uint32_t smem_u32(const void* p) {
    uint32_t a;
    asm("{ .reg .u64 t; cvta.to.shared.u64 t, %1; cvt.u32.u64 %0, t; }"
        : "=r"(a) : "l"(p));
    return a;
}

__device__ __forceinline__ void ldm4(uint32_t addr, uint32_t* r) {
    asm volatile("ldmatrix.sync.aligned.m8n8.x4.shared.b16 {%0,%1,%2,%3}, [%4];"
                 : "=r"(r[0]), "=r"(r[1]), "=r"(r[2]), "=r"(r[3]) : "r"(addr));
}

__device__ __forceinline__ void mma16(float* c, const uint32_t* a,
                                      uint32_t b0, uint32_t b1) {
    asm volatile(
        "mma.sync.aligned.m16n8k16.row.col.f32.f16.f16.f32 "
        "{%0,%1,%2,%3}, {%4,%5,%6,%7}, {%8,%9}, {%0,%1,%2,%3};"
        : "+f"(c[0]), "+f"(c[1]), "+f"(c[2]), "+f"(c[3])
        : "r"(a[0]), "r"(a[1]), "r"(a[2]), "r"(a[3]), "r"(b0), "r"(b1));
}

__device__ __forceinline__ uint2 pack_h4(const float4& v) {
    __half2 h0 = __floats2half2_rn(v.x, v.y);
    __half2 h1 = __floats2half2_rn(v.z, v.w);
    uint2 r;
    r.x = *(const uint32_t*)&h0;
    r.y = *(const uint32_t*)&h1;
    return r;
}

// convert-at-store: keeps LDG results untouched in regs for a full chunk
__device__ __forceinline__ void sts_h4(uint32_t addr, const float4& v) {
    uint2 p = pack_h4(v);
    asm volatile("st.shared.v2.b32 [%0], {%1,%2};"
                 :: "r"(addr), "r"(p.x), "r"(p.y) : "memory");
}

__device__ __forceinline__ void sts_u2(uint32_t addr, uint2 v) {
    asm volatile("st.shared.v2.b32 [%0], {%1,%2};"
                 :: "r"(addr), "r"(v.x), "r"(v.y) : "memory");
}

#define CPA16(dst, src, sz) \
    asm volatile("cp.async.cg.shared.global [%0], [%1], 16, %2;" \
                 :: "r"(dst), "l"(src), "r"(sz) : "memory")
#define CPC()  asm volatile("cp.async.commit_group;" ::: "memory")
#define CPW0() asm volatile("cp.async.wait_group 0;" ::: "memory")

// ---------------- routing ----------------------------------------------------
__global__ void routing_kernel(const int* __restrict__ sel) {
    __shared__ int s_cnt[NE], s_off[NE], s_cur[NE];
    const int tid = threadIdx.x;
    if (tid < NE) s_cnt[tid] = 0;
    __syncthreads();
    for (int p = tid; p < NPAIR; p += blockDim.x)
        atomicAdd(&s_cnt[sel[p]], 1);
    __syncthreads();
    if (tid == 0) {
        int acc = 0;
        for (int e = 0; e < NE; e++) { s_off[e] = acc; acc += s_cnt[e]; s_cur[e] = 0; }
    }
    __syncthreads();
    for (int p = tid; p < NPAIR; p += blockDim.x) {
        int e = sel[p];
        int pos = atomicAdd(&s_cur[e], 1);
        g_list[s_off[e] + pos] = p;
    }
    if (tid < NE) { g_cnt[tid] = s_cnt[tid]; g_off[tid] = s_off[tid]; }
}

// ---------------- x -> fp16 pre-pass -----------------------------------------
__global__ void xcvt_kernel(const float* __restrict__ x) {
    const int i = blockIdx.x * blockDim.x + threadIdx.x;
    if (i >= NT * NH / 8) return;
    const float4 v0 = *(const float4*)(x + (size_t)i * 8);
    const float4 v1 = *(const float4*)(x + (size_t)i * 8 + 4);
    uint2 a = pack_h4(v0), b = pack_h4(v1);
    uint4 o; o.x = a.x; o.y = a.y; o.z = b.x; o.w = b.y;
    g_xh_raw[i] = o;
}

extern __shared__ char dynsm[];

// ---------------- GEMM1: gate+up fused, 128x128 CTA, 2m x 4n (R13 verbatim) --
__global__ void __launch_bounds__(256) gemm1_kernel(
    int ebase,
    const float* __restrict__ wg, const float* __restrict__ sg,
    const float* __restrict__ wu, const float* __restrict__ su)
{
    const int e   = ebase + blockIdx.z;
    const int cnt = g_cnt[e];
    const int m0  = blockIdx.y * 128;
    if (m0 >= cnt) return;
    const int eoff = g_off[e];
    const int n0   = blockIdx.x * 128;
    const int tid  = threadIdx.x;

    int* s_tok = (int*)dynsm;
    const uint32_t hb = smem_u32(dynsm) + 1024;

    if (tid < 128) {
        int mi = m0 + tid;
        s_tok[tid] = (mi < cnt) ? (g_list[eoff + mi] / NK) : -1;
    }
    __syncthreads();

    const float* wge = wg + (size_t)e * NI * NH + (size_t)n0 * NH;
    const float* wue = wu + (size_t)e * NI * NH + (size_t)n0 * NH;
    const int scb = e * (NI / QB) * (NH / QB) + (n0 >> 7) * (NH / QB);

    // weight staging as raw float4; conversion deferred to STS (latency hiding)
    float4 Rg[4], Ru[4];
    const int ldrow = tid >> 3, ldcc = tid & 7;

    auto ldgW = [&](int c) {
        const int k0 = c * 32;
#pragma unroll
        for (int it = 0; it < 4; ++it) {
            const int row = ldrow + it * 32;
            Rg[it] = *(const float4*)(wge + (size_t)row * NH + k0 + (ldcc << 2));
            Ru[it] = *(const float4*)(wue + (size_t)row * NH + k0 + (ldcc << 2));
        }
    };
    auto stsW = [&](uint32_t stage) {
#pragma unroll
        for (int it = 0; it < 4; ++it) {
            const uint32_t off = (uint32_t)((ldrow + it * 32) * HSTRIDE + ldcc * 8);
            sts_h4(stage + HTILE + off, Rg[it]);
            sts_h4(stage + 2 * HTILE + off, Ru[it]);
        }
    };
    auto cpaA = [&](int c, uint32_t stage) {
        const int k0 = c * 32;
#pragma unroll
        for (int it = 0; it < 2; ++it) {
            const int idx = tid + (it << 8);
            const int row = idx >> 2, cc = idx & 3;
            const int tok = s_tok[row];
            const __half* src = g_xh + (size_t)(tok >= 0 ? tok : 0) * NH + k0 + cc * 8;
            CPA16(stage + (uint32_t)(row * HSTRIDE + cc * 16), src, (tok >= 0) ? 16 : 0);
        }
        CPC();
    };

    const int lane = tid & 31, warp = tid >> 5;
    const int gq = lane >> 2, tq = lane & 3;
    const int wm = warp & 1, wn = warp >> 1;   // 2 m-warps x 4 n-warps (64x32 tiles)
    const int lrow = lane & 15, lcol = (lane >> 4) << 4;

    float accG[4][4][4];
    float accU[4][4][4];
#pragma unroll
    for (int mi = 0; mi < 4; mi++)
#pragma unroll
        for (int ni = 0; ni < 4; ni++)
#pragma unroll
            for (int q = 0; q < 4; q++) { accG[mi][ni][q] = 0.f; accU[mi][ni][q] = 0.f; }

    float sg_c = __ldg(sg + scb);
    float su_c = __ldg(su + scb);

    const int C = NH / 32;   // 64 chunks, 4 per quant block

    ldgW(0);
    stsW(hb);
    cpaA(0, hb);
    ldgW(1);
    CPW0();
    __syncthreads();

    for (int c = 0; c < C; ++c) {
        const uint32_t Ss = hb + (uint32_t)((c & 1) * HSTG1);
        const uint32_t So = hb + (uint32_t)(((c + 1) & 1) * HSTG1);
        if (c + 1 < C) {
            stsW(So);                 // regs hold chunk c+1
            cpaA(c + 1, So);
            if (c + 2 < C) ldgW(c + 2);
        }

        const uint32_t hA = Ss, hG = Ss + HTILE, hU = Ss + 2 * HTILE;
#pragma unroll
        for (int ks = 0; ks < 2; ks++) {
            const uint32_t kc = (uint32_t)(ks * 32 + lcol);
            uint32_t a[4][4];
#pragma unroll
            for (int mi = 0; mi < 4; mi++)
                ldm4(hA + (uint32_t)((wm * 64 + mi * 16 + lrow) * HSTRIDE) + kc, a[mi]);
#pragma unroll
            for (int nbg = 0; nbg < 2; nbg++) {
                const uint32_t rowb = (uint32_t)((wn * 32 + nbg * 16 + lrow) * HSTRIDE) + kc;
                uint32_t g[4], u[4];
                ldm4(hG + rowb, g);
                ldm4(hU + rowb, u);
#pragma unroll
                for (int mi = 0; mi < 4; mi++) {
                    mma16(accG[mi][2 * nbg + 0], a[mi], g[0], g[2]);
                    mma16(accG[mi][2 * nbg + 1], a[mi], g[1], g[3]);
                    mma16(accU[mi][2 * nbg + 0], a[mi], u[0], u[2]);
                    mma16(accU[mi][2 * nbg + 1], a[mi], u[1], u[3]);
                }
            }
        }

        if ((c & 3) == 3 && c + 1 < C) {
            const int b = (c >> 2) + 1;
            const float sgn = __ldg(sg + scb + b);
            const float sun = __ldg(su + scb + b);
            const float rg = sg_c / sgn, ru = su_c / sun;
            sg_c = sgn; su_c = sun;
#pragma unroll
            for (int mi = 0; mi < 4; mi++)
#pragma unroll
                for (int ni = 0; ni < 4; ni++)
#pragma unroll
                    for (int q = 0; q < 4; q++) {
                        accG[mi][ni][q] *= rg;
                        accU[mi][ni][q] *= ru;
                    }
        }

        if (c + 1 < C) CPW0();
        __syncthreads();
    }

    // epilogue: final scale + SwiGLU -> fp16 sorted activations
#pragma unroll
    for (int mi = 0; mi < 4; mi++) {
#pragma unroll
        for (int half = 0; half < 2; half++) {
            const int rr = wm * 64 + mi * 16 + gq + half * 8;
            const int gm = m0 + rr;
            if (gm < cnt) {
                __half* dst = g_hact + (size_t)(eoff + gm) * NI + n0 + wn * 32 + 2 * tq;
#pragma unroll
                for (int ni = 0; ni < 4; ni++) {
                    float g0 = accG[mi][ni][half * 2 + 0] * sg_c;
                    float g1 = accG[mi][ni][half * 2 + 1] * sg_c;
                    float u0 = accU[mi][ni][half * 2 + 0] * su_c;
                    float u1 = accU[mi][ni][half * 2 + 1] * su_c;
                    float h0 = g0 / (1.f + __expf(-g0)) * u0;
                    float h1 = g1 / (1.f + __expf(-g1)) * u1;
                    __half2 h = __floats2half2_rn(h0, h1);
                    *(uint32_t*)(dst + ni * 8) = *(uint32_t*)&h;
                }
            }
        }
    }
}

// ---------------- GEMM2: down proj (R7 proven), fp16 ypair output ------------
__global__ void __launch_bounds__(256, 2) gemm2_kernel(
    int ebase,
    const float* __restrict__ wd, const float* __restrict__ sd,
    const float* __restrict__ rw)
{
    const int e   = ebase + blockIdx.z;
    const int cnt = g_cnt[e];
    const int m0  = blockIdx.y * 128;
    if (m0 >= cnt) return;
    const int eoff = g_off[e];
    const int n0   = blockIdx.x * 128;
    const int tid  = threadIdx.x;

    int*   s_pair = (int*)dynsm;
    float* s_rw   = (float*)(dynsm + 512);
    const uint32_t hb = smem_u32(dynsm) + 1024;

    if (tid < 128) {
        int mi = m0 + tid;
        int p = (mi < cnt) ? g_list[eoff + mi] : -1;
        s_pair[tid] = p;
        s_rw[tid]   = (p >= 0) ? rw[p] : 0.f;
    }
    __syncthreads();

    const float* wde = wd + (size_t)e * NH * NI + (size_t)n0 * NI;
    const int scb = e * (NH / QB) * (NI / QB) + (n0 >> 7) * (NI / QB);

    // raw float4 staging; conversion at STS (same latency-hiding discipline)
    float4 Rb[4];
    const int ldrow = tid >> 3, ldcc = tid & 7;

    auto ldgW = [&](int c) {
        const int k0 = c * 32;
#pragma unroll
        for (int it = 0; it < 4; ++it)
            Rb[it] = *(const float4*)(wde + (size_t)(ldrow + it * 32) * NI + k0 + (ldcc << 2));
    };
    auto stsW = [&](uint32_t stage) {
#pragma unroll
        for (int it = 0; it < 4; ++it)
            sts_h4(stage + HTILE + (uint32_t)((ldrow + it * 32) * HSTRIDE + ldcc * 8), Rb[it]);
    };
    auto cpaA = [&](int c, uint32_t stage) {
        const int k0 = c * 32;
#pragma unroll
        for (int it = 0; it < 2; ++it) {
            const int idx = tid + (it << 8);
            const int row = idx >> 2, cc = idx & 3;
            const int ok = (m0 + row < cnt) ? 16 : 0;
            const __half* src = g_hact + (size_t)(eoff + m0 + row) * NI + k0 + cc * 8;
            CPA16(stage + (uint32_t)(row * HSTRIDE + cc * 16), src, ok);
        }
        CPC();
    };

    const int lane = tid & 31, warp = tid >> 5;
    const int gq = lane >> 2, tq = lane & 3;
    const int wm = warp & 3, wn = warp >> 2;   // 4 m-warps x 2 n-warps
    const int lrow = lane & 15, lcol = (lane >> 4) << 4;

    float acc[2][8][4];
#pragma unroll
    for (int mi = 0; mi < 2; mi++)
#pragma unroll
        for (int ni = 0; ni < 8; ni++)
#pragma unroll
            for (int q = 0; q < 4; q++) acc[mi][ni][q] = 0.f;

    float sd_c = __ldg(sd + scb);

    const int C = NI / 32;   // 44 chunks

    ldgW(0);
    stsW(hb);
    cpaA(0, hb);
    ldgW(1);
    CPW0();
    __syncthreads();

    for (int c = 0; c < C; ++c) {
        const uint32_t Ss = hb + (uint32_t)((c & 1) * HSTG);
        const uint32_t So = hb + (uint32_t)(((c + 1) & 1) * HSTG);
        if (c + 1 < C) {
            stsW(So);
            cpaA(c + 1, So);
            if (c + 2 < C) ldgW(c + 2);
        }

        const uint32_t hA = Ss, hB = Ss + HTILE;
#pragma unroll
        for (int ks = 0; ks < 2; ks++) {
            const uint32_t kc = (uint32_t)(ks * 32 + lcol);
            uint32_t a[2][4];
#pragma unroll
            for (int mi = 0; mi < 2; mi++)
                ldm4(hA + (uint32_t)((wm * 32 + mi * 16 + lrow) * HSTRIDE) + kc, a[mi]);
#pragma unroll
            for (int nb = 0; nb < 4; nb++) {
                const uint32_t rowb = (uint32_t)((wn * 64 + nb * 16 + lrow) * HSTRIDE) + kc;
                uint32_t b[4];
                ldm4(hB + rowb, b);
#pragma unroll
                for (int mi = 0; mi < 2; mi++) {
                    mma16(acc[mi][2 * nb + 0], a[mi], b[0], b[2]);
                    mma16(acc[mi][2 * nb + 1], a[mi], b[1], b[3]);
                }
            }
        }

        if ((c & 3) == 3 && c + 1 < C) {
            const int b = (c >> 2) + 1;
            const float sdn = __ldg(sd + scb + b);
            const float rsc = sd_c / sdn;
            sd_c = sdn;
#pragma unroll
            for (int mi = 0; mi < 2; mi++)
#pragma unroll
                for (int ni = 0; ni < 8; ni++)
#pragma unroll
                    for (int q = 0; q < 4; q++) acc[mi][ni][q] *= rsc;
        }

        if (c + 1 < C) CPW0();
        __syncthreads();
    }

#pragma unroll
    for (int mi = 0; mi < 2; mi++) {
#pragma unroll
        for (int half = 0; half < 2; half++) {
            const int rr = wm * 32 + mi * 16 + gq + half * 8;
            const int gm = m0 + rr;
            if (gm < cnt) {
                const int p = s_pair[gm - m0];
                const float w = s_rw[gm - m0] * sd_c;
                if (p >= 0) {
                    __half* dst = g_ypair + (size_t)p * NH + n0 + wn * 64 + 2 * tq;
#pragma unroll
                    for (int ni = 0; ni < 8; ni++) {
                        __half2 h = __floats2half2_rn(acc[mi][ni][half * 2 + 0] * w,
                                                      acc[mi][ni][half * 2 + 1] * w);
                        *(uint32_t*)(dst + ni * 8) = *(uint32_t*)&h;
                    }
                }
            }
        }
    }
}

// ---------------- combine (fp16 ypair -> fp32 out) ---------------------------
__global__ void combine_kernel(float* __restrict__ out) {
    const int idx = blockIdx.x * blockDim.x + threadIdx.x;
    if (idx >= NT * NH / 4) return;
    const int t  = idx / (NH / 4);
    const int h4 = idx - t * (NH / 4);
    float4 s = make_float4(0.f, 0.f, 0.f, 0.f);
#pragma unroll
    for (int k = 0; k < NK; k++) {
        const uint2 v = *(const uint2*)(g_ypair + (size_t)(t * NK + k) * NH + h4 * 4);
        const __half2 a = *(const __half2*)&v.x;
        const __half2 b = *(const __half2*)&v.y;
        s.x += __low2float(a); s.y += __high2float(a);
        s.z += __low2float(b); s.w += __high2float(b);
    }
    *(float4*)(out + (size_t)t * NH + h4 * 4) = s;
}

// ---------------- launch -----------------------------------------------------
#define SMEM1 (1024 + 2 * HSTG1)  // 62464
#define SMEM2 (1024 + 2 * HSTG)   // 41984

extern "C" void kernel_launch(void* const* d_in, const int* in_sizes, int n_in,
                              void* d_out, int out_size) {
    const float* x   = (const float*)d_in[0];
    const float* gw  = (const float*)d_in[1];
    const float* gsc = (const float*)d_in[2];
    const float* uw  = (const float*)d_in[3];
    const float* usc = (const float*)d_in[4];
    const float* dw  = (const float*)d_in[5];
    const float* dsc = (const float*)d_in[6];
    const float* rw  = (const float*)d_in[7];
    const int*   sel = (const int*)d_in[8];
    float* out = (float*)d_out;

    static cudaStream_t s2 = nullptr;
    static cudaEvent_t  evF = nullptr, evJ = nullptr;
    static int configured = 0;
    if (!configured) {
        cudaFuncSetAttribute(gemm1_kernel, cudaFuncAttributeMaxDynamicSharedMemorySize, SMEM1);
        cudaFuncSetAttribute(gemm2_kernel, cudaFuncAttributeMaxDynamicSharedMemorySize, SMEM2);
        cudaStreamCreateWithFlags(&s2, cudaStreamNonBlocking);
        cudaEventCreateWithFlags(&evF, cudaEventDisableTiming);
        cudaEventCreateWithFlags(&evJ, cudaEventDisableTiming);
        configured = 1;
    }

    routing_kernel<<<1, 256>>>(sel);
    xcvt_kernel<<<(NT * NH / 8 + 255) / 256, 256>>>(x);

    // fork: side stream handles experts 8..15
    cudaEventRecord(evF, 0);
    cudaStreamWaitEvent(s2, evF, 0);

    dim3 g1(NI / 128, NPAIR / 128, NE / 2);   // (11, 24, 8)
    gemm1_kernel<<<g1, 256, SMEM1, 0 >>>(0, gw, gsc, uw, usc);
    gemm1_kernel<<<g1, 256, SMEM1, s2>>>(8, gw, gsc, uw, usc);

    dim3 g2(NH / 128, NPAIR / 128, NE / 2);   // (16, 24, 8)
    gemm2_kernel<<<g2, 256, SMEM2, 0 >>>(0, dw, dsc, rw);
    gemm2_kernel<<<g2, 256, SMEM2, s2>>>(8, dw, dsc, rw);

    // join
    cudaEventRecord(evJ, s2);
    cudaStreamWaitEvent(0, evJ, 0);

    combine_kernel<<<(NT * NH / 4 + 255) / 256, 256>>>(out);
}